// round 6
// baseline (speedup 1.0000x reference)
#include <cuda_runtime.h>
#include <mma.h>

using namespace nvcuda;

#define NN    100000
#define EE    1600000
#define HID   64
#define HID2  128
#define EDIM  16
#define INDIM 32

// ---------------- scratch (device globals; no allocation) ----------------
__device__ float      g_hA[NN * HID];
__device__ float      g_hB[NN * HID];
__device__ float      g_tmp[NN * HID];
__device__ int        g_deg[NN];
__device__ int        g_cnt[NN];
__device__ int        g_rowptr[NN + 1];
__device__ int        g_blksum[256];
__device__ int        g_srcp[EE];        // src index in CSR order
__device__ int        g_eperm[EE];       // CSR position -> original edge id
__device__ ulonglong2 g_eap[EE * 4];     // pair-interleaved edge_attr, 128 B/pair

// ---------------- packed f32x2 helpers ----------------
union PF { float2 f2; unsigned long long u; };

__device__ __forceinline__ unsigned long long fma2(unsigned long long a,
                                                   unsigned long long b,
                                                   unsigned long long c) {
    unsigned long long d;
    asm("fma.rn.f32x2 %0, %1, %2, %3;" : "=l"(d) : "l"(a), "l"(b), "l"(c));
    return d;
}
__device__ __forceinline__ unsigned long long dup2(float x) {
    unsigned long long d; unsigned int r = __float_as_uint(x);
    asm("mov.b64 %0, {%1, %1};" : "=l"(d) : "r"(r));
    return d;
}

// tf32 round-to-nearest
__device__ __forceinline__ float tf32r(float x) {
    unsigned int u = __float_as_uint(x);
    u = (u + 0x1000u) & 0xFFFFE000u;
    return __uint_as_float(u);
}

// ---------------- CSR build ----------------
__global__ void k_zero(int N) {
    int i = blockIdx.x * blockDim.x + threadIdx.x;
    if (i < N) { g_deg[i] = 0; g_cnt[i] = 0; }
}

__global__ void k_hist(const int* __restrict__ dst, int E) {
    int e = blockIdx.x * blockDim.x + threadIdx.x;
    if (e < E) atomicAdd(&g_deg[dst[e]], 1);
}

__global__ void k_scan1(int N) {
    __shared__ int sh[1024];
    int i = blockIdx.x * 1024 + threadIdx.x;
    int v = (i < N) ? g_deg[i] : 0;
    sh[threadIdx.x] = v;
    __syncthreads();
    for (int off = 1; off < 1024; off <<= 1) {
        int add = (threadIdx.x >= off) ? sh[threadIdx.x - off] : 0;
        __syncthreads();
        sh[threadIdx.x] += add;
        __syncthreads();
    }
    if (i < N) g_rowptr[i] = sh[threadIdx.x] - v;     // exclusive
    if (threadIdx.x == 1023) g_blksum[blockIdx.x] = sh[1023];
}

__global__ void k_scan2(int B) {
    if (blockIdx.x == 0 && threadIdx.x == 0) {
        int acc = 0;
        for (int b = 0; b < B; b++) { int t = g_blksum[b]; g_blksum[b] = acc; acc += t; }
    }
}

__global__ void k_scan3(int N, int E) {
    int i = blockIdx.x * 1024 + threadIdx.x;
    if (i < N) g_rowptr[i] += g_blksum[blockIdx.x];
    if (i == 0) g_rowptr[N] = E;
}

// scatter: CSR-permute src + record permutation (8 B/edge of scattered writes)
__global__ void k_scatter(const int* __restrict__ src, const int* __restrict__ dst, int E) {
    int e = blockIdx.x * blockDim.x + threadIdx.x;
    if (e >= E) return;
    int d = dst[e];
    int p = g_rowptr[d] + atomicAdd(&g_cnt[d], 1);
    g_srcp[p]  = src[e];
    g_eperm[p] = e;
}

// interleave: one thread per CSR pair; gather 2 edges' attrs, write k-interleaved
__global__ void k_interleave(const float4* __restrict__ ea, int E) {
    int q = blockIdx.x * blockDim.x + threadIdx.x;
    if (q >= (E >> 1)) return;
    int e0 = g_eperm[2 * q], e1 = g_eperm[2 * q + 1];
    float4 A[4], B[4];
#pragma unroll
    for (int j = 0; j < 4; j++) { A[j] = __ldg(ea + e0 * 4 + j); B[j] = __ldg(ea + e1 * 4 + j); }
    float4* out = (float4*)g_eap + (size_t)q * 8;
#pragma unroll
    for (int j = 0; j < 4; j++) {
        out[2 * j + 0] = make_float4(A[j].x, B[j].x, A[j].y, B[j].y);
        out[2 * j + 1] = make_float4(A[j].z, B[j].z, A[j].w, B[j].w);
    }
}

// ---------------- input linear: h = x @ src_w + src_b ----------------
__global__ void k_inlin(const float* __restrict__ x, const float* __restrict__ w,
                        const float* __restrict__ b, int N) {
    int idx = blockIdx.x * blockDim.x + threadIdx.x;
    if (idx >= N * HID) return;
    int n = idx >> 6, c = idx & 63;
    const float* xr = x + n * INDIM;
    float acc = __ldg(&b[c]);
#pragma unroll
    for (int k = 0; k < INDIM; k++)
        acc = fmaf(__ldg(&xr[k]), __ldg(&w[k * HID + c]), acc);
    g_hA[idx] = acc;
}

// ---------------- aggregation ----------------
// 2 warps per node (each owns 32 channels, 1 per lane); edges processed in pairs
// packed into f32x2. No max-subtraction (messages are small, exp-safe).
__global__ void __launch_bounds__(256)
k_agg(int dir, const float* __restrict__ ew, const float* __restrict__ ebias, int N) {
    const float* hin = dir ? g_hB : g_hA;
    int warp = threadIdx.x >> 5, lane = threadIdx.x & 31;
    int n = blockIdx.x * 4 + (warp >> 1);
    if (n >= N) return;
    int c = ((warp & 1) << 5) + lane;

    // duplicated weight pairs (w,w) for this lane's channel
    unsigned long long ewd[EDIM];
#pragma unroll
    for (int k = 0; k < EDIM; k++)
        ewd[k] = dup2(__ldg(&ew[k * HID + c]));
    unsigned long long ebd = dup2(__ldg(&ebias[c]));

    int beg = g_rowptr[n], end = g_rowptr[n + 1];
    int qb = beg >> 1, qe = (end + 1) >> 1;

    float s = 0.f, t = 0.f;

#pragma unroll 2
    for (int q = qb; q < qe; q++) {
        int2 sv = __ldg((const int2*)g_srcp + q);
        const ulonglong2* ep = g_eap + (size_t)q * 8;   // 128 B per pair (FIXED stride)
        unsigned long long acc = ebd;
#pragma unroll
        for (int j = 0; j < 4; j++) {
            ulonglong2 Q = __ldg(ep + j);
            acc = fma2(Q.x, ewd[2 * j + 0], acc);
            acc = fma2(Q.y, ewd[2 * j + 1], acc);
        }
        const ulonglong2* ep2 = ep + 4;                 // k = 8..15
#pragma unroll
        for (int j = 0; j < 4; j++) {
            ulonglong2 Q = __ldg(ep2 + j);
            acc = fma2(Q.x, ewd[8 + 2 * j + 0], acc);
            acc = fma2(Q.y, ewd[8 + 2 * j + 1], acc);
        }
        float h0 = __ldg(&hin[sv.x * HID + c]);
        float h1 = __ldg(&hin[sv.y * HID + c]);
        PF a; a.u = acc;
        float msg0 = fmaxf(a.f2.x + h0, 0.f);
        float msg1 = fmaxf(a.f2.y + h1, 0.f);
        if (2 * q < beg)       msg0 = -1000.f;   // pair head belongs to prev node
        if (2 * q + 1 >= end)  msg1 = -1000.f;   // pair tail belongs to next node
        float w0 = __expf(msg0);
        float w1 = __expf(msg1);
        s += w0 + w1;
        t = fmaf(msg0, w0, t);
        t = fmaf(msg1, w1, t);
    }

    float hs = __ldg(&hin[n * HID + c]);
    float o = (s > 0.f ? __fdividef(t, s) + 1e-7f : 0.f) + hs;
    g_tmp[n * HID + c] = o;
}

// ---------------- MLP via tf32 tensor cores (64 nodes / block) ----------------
__global__ void __launch_bounds__(256)
k_mlp(int dir,
      const float* __restrict__ w1, const float* __restrict__ b1,
      const float* __restrict__ gam, const float* __restrict__ bet,
      const float* __restrict__ w2, const float* __restrict__ b2, int N) {
    float* outp = dir ? g_hA : g_hB;
    extern __shared__ float sm[];
    float* s_x  = sm;                     // [64][64]
    float* s_w1 = sm + 4096;              // [64][128]
    float* s_h  = sm + 4096 + 8192;       // [64][128]
    float* s_w2 = sm + 4096 + 16384;      // [128][64]

    int tid  = threadIdx.x;
    int base = blockIdx.x * 64;

    for (int i = tid; i < 8192; i += 256) s_w1[i] = tf32r(__ldg(&w1[i]));
    for (int i = tid; i < 8192; i += 256) s_w2[i] = tf32r(__ldg(&w2[i]));
    {
        const float4* in4 = (const float4*)(g_tmp + base * HID);
        long limit4 = (long)(N - base) * 16;
        for (int i = tid; i < 1024; i += 256) {
            float4 v = (i < limit4) ? __ldg(in4 + i) : make_float4(0.f, 0.f, 0.f, 0.f);
            v.x = tf32r(v.x); v.y = tf32r(v.y); v.z = tf32r(v.z); v.w = tf32r(v.w);
            ((float4*)s_x)[i] = v;
        }
    }
    __syncthreads();

    int wid = tid >> 5;
    int mt  = wid >> 1;

    // phase 1: H[64x128] = X[64x64] @ W1[64x128]
    {
        int nb = (wid & 1) * 4;
        wmma::fragment<wmma::accumulator, 16, 16, 8, float> c[4];
#pragma unroll
        for (int t = 0; t < 4; t++) wmma::fill_fragment(c[t], 0.f);
#pragma unroll
        for (int k = 0; k < 8; k++) {
            wmma::fragment<wmma::matrix_a, 16, 16, 8, wmma::precision::tf32, wmma::row_major> a;
            wmma::load_matrix_sync(a, s_x + mt * 16 * 64 + k * 8, 64);
#pragma unroll
            for (int t = 0; t < 4; t++) {
                wmma::fragment<wmma::matrix_b, 16, 16, 8, wmma::precision::tf32, wmma::row_major> b;
                wmma::load_matrix_sync(b, s_w1 + (k * 8) * 128 + (nb + t) * 16, 128);
                wmma::mma_sync(c[t], a, b, c[t]);
            }
        }
#pragma unroll
        for (int t = 0; t < 4; t++)
            wmma::store_matrix_sync(s_h + mt * 16 * 128 + (nb + t) * 16, c[t], 128,
                                    wmma::mem_row_major);
    }
    __syncthreads();

    // BN + ReLU
    {
        const float BNC = 0.9999950000375f;
        for (int i = tid; i < 8192; i += 256) {
            int j = i & 127;
            float v = s_h[i] + __ldg(&b1[j]);
            v = fmaf(v, __ldg(&gam[j]) * BNC, __ldg(&bet[j]));
            s_h[i] = tf32r(fmaxf(v, 0.f));
        }
    }
    __syncthreads();

    // phase 2: O[64x64] = H[64x128] @ W2[128x64]
    {
        int nb = (wid & 1) * 2;
        wmma::fragment<wmma::accumulator, 16, 16, 8, float> c[2];
#pragma unroll
        for (int t = 0; t < 2; t++) wmma::fill_fragment(c[t], 0.f);
#pragma unroll
        for (int k = 0; k < 16; k++) {
            wmma::fragment<wmma::matrix_a, 16, 16, 8, wmma::precision::tf32, wmma::row_major> a;
            wmma::load_matrix_sync(a, s_h + mt * 16 * 128 + k * 8, 128);
#pragma unroll
            for (int t = 0; t < 2; t++) {
                wmma::fragment<wmma::matrix_b, 16, 16, 8, wmma::precision::tf32, wmma::row_major> b;
                wmma::load_matrix_sync(b, s_w2 + (k * 8) * 64 + (nb + t) * 16, 64);
                wmma::mma_sync(c[t], a, b, c[t]);
            }
        }
#pragma unroll
        for (int t = 0; t < 2; t++)
            wmma::store_matrix_sync(s_x + mt * 16 * 64 + (nb + t) * 16, c[t], 64,
                                    wmma::mem_row_major);
    }
    __syncthreads();

    {
        const float4* b24 = (const float4*)b2;
        for (int i = tid; i < 1024; i += 256) {
            int row = i >> 4, c4 = i & 15;
            int node = base + row;
            if (node < N) {
                float4 v  = ((float4*)s_x)[i];
                float4 bb = __ldg(&b24[c4]);
                v.x = fmaxf(v.x + bb.x, 0.f);
                v.y = fmaxf(v.y + bb.y, 0.f);
                v.z = fmaxf(v.z + bb.z, 0.f);
                v.w = fmaxf(v.w + bb.w, 0.f);
                ((float4*)(outp + node * HID))[c4] = v;
            }
        }
    }
}

// ---------------- head ----------------
__global__ void k_head(const float* __restrict__ gfeat, const int* __restrict__ ngp,
                       const float* __restrict__ hw, const float* __restrict__ hb,
                       float* __restrict__ out, int N, int gfd) {
    int n = blockIdx.x * blockDim.x + threadIdx.x;
    if (n >= N) return;
    const float* h = g_hA;
    float acc = __ldg(&hb[0]);
#pragma unroll 8
    for (int c = 0; c < HID; c++)
        acc = fmaf(h[n * HID + c], __ldg(&hw[c]), acc);
    int G = *ngp;
    int npg = N / G;
    int g = n / npg, r = n - g * npg;
    for (int d = 0; d < gfd; d++)
        acc = fmaf(__ldg(&gfeat[(g * gfd + d) * npg + r]), __ldg(&hw[HID + d]), acc);
    out[n] = acc;
}

// ---------------- launch ----------------
extern "C" void kernel_launch(void* const* d_in, const int* in_sizes, int n_in,
                              void* d_out, int out_size) {
    const float* x     = (const float*)d_in[0];
    const int*   eidx  = (const int*)d_in[1];
    const float* eattr = (const float*)d_in[2];
    const int*   ngp   = (const int*)d_in[3];
    const float* gfeat = (const float*)d_in[4];
    const float* src_w = (const float*)d_in[5];
    const float* src_b = (const float*)d_in[6];

    int N   = in_sizes[0] / INDIM;
    int E   = in_sizes[1] / 2;
    int gfd = in_sizes[4] / N;

    const int* src = eidx;
    const int* dst = eidx + E;

    const int MLP_SMEM = (4096 + 8192 + 8192 + 8192) * 4;   // 114688 B
    cudaFuncSetAttribute(k_mlp, cudaFuncAttributeMaxDynamicSharedMemorySize, MLP_SMEM);

    // CSR build + pair-interleaved edge stream
    k_zero<<<(N + 255) / 256, 256>>>(N);
    k_hist<<<(E + 255) / 256, 256>>>(dst, E);
    int nb = (N + 1023) / 1024;
    k_scan1<<<nb, 1024>>>(N);
    k_scan2<<<1, 32>>>(nb);
    k_scan3<<<nb, 1024>>>(N, E);
    k_scatter<<<(E + 255) / 256, 256>>>(src, dst, E);
    k_interleave<<<(E / 2 + 255) / 256, 256>>>((const float4*)eattr, E);

    // h0 = x @ src_w + src_b (writes g_hA)
    k_inlin<<<(N * HID + 255) / 256, 256>>>(x, src_w, src_b, N);

    // layer 0: hA -> tmp -> hB
    k_agg<<<(N + 3) / 4, 256>>>(0, (const float*)d_in[7], (const float*)d_in[8], N);
    k_mlp<<<(N + 63) / 64, 256, MLP_SMEM>>>(0,
        (const float*)d_in[9],  (const float*)d_in[10],
        (const float*)d_in[11], (const float*)d_in[12],
        (const float*)d_in[13], (const float*)d_in[14], N);

    // layer 1: hB -> tmp -> hA
    k_agg<<<(N + 3) / 4, 256>>>(1, (const float*)d_in[15], (const float*)d_in[16], N);
    k_mlp<<<(N + 63) / 64, 256, MLP_SMEM>>>(1,
        (const float*)d_in[17], (const float*)d_in[18],
        (const float*)d_in[19], (const float*)d_in[20],
        (const float*)d_in[21], (const float*)d_in[22], N);

    // head
    k_head<<<(N + 255) / 256, 256>>>(gfeat, ngp,
        (const float*)d_in[23], (const float*)d_in[24],
        (float*)d_out, N, gfd);
    (void)n_in; (void)out_size;
}

// round 8
// speedup vs baseline: 1.2671x; 1.2671x over previous
#include <cuda_runtime.h>

#define NN    100000
#define EE    1600000
#define HID   64
#define HID2  128
#define EDIM  16
#define INDIM 32

// ---------------- scratch (device globals; no allocation) ----------------
__device__ float  g_hA[NN * HID];
__device__ float  g_hB[NN * HID];
__device__ float  g_tmp[NN * HID];
__device__ int    g_deg[NN];
__device__ int    g_cnt[NN];
__device__ int    g_rowptr[NN + 1];
__device__ int    g_blksum[256];
__device__ int    g_srcp[EE];          // src index permuted to CSR order
__device__ float4 g_eap[EE * 4];       // edge_attr permuted to CSR order (64 B/edge)

// ---------------- packed f32x2 helpers ----------------
union PF { float2 f2; unsigned long long u; };

__device__ __forceinline__ unsigned long long fma2(unsigned long long a,
                                                   unsigned long long b,
                                                   unsigned long long c) {
    unsigned long long d;
    asm("fma.rn.f32x2 %0, %1, %2, %3;" : "=l"(d) : "l"(a), "l"(b), "l"(c));
    return d;
}
__device__ __forceinline__ unsigned long long pack2(float lo, float hi) {
    unsigned long long d;
    asm("mov.b64 %0, {%1, %2};" : "=l"(d)
        : "r"(__float_as_uint(lo)), "r"(__float_as_uint(hi)));
    return d;
}

// ---------------- CSR build ----------------
__global__ void k_zero(int N) {
    int i = blockIdx.x * blockDim.x + threadIdx.x;
    if (i < N) { g_deg[i] = 0; g_cnt[i] = 0; }
}

__global__ void k_hist(const int* __restrict__ dst, int E) {
    int e = blockIdx.x * blockDim.x + threadIdx.x;
    if (e < E) atomicAdd(&g_deg[dst[e]], 1);
}

__global__ void k_scan1(int N) {
    __shared__ int sh[1024];
    int i = blockIdx.x * 1024 + threadIdx.x;
    int v = (i < N) ? g_deg[i] : 0;
    sh[threadIdx.x] = v;
    __syncthreads();
    for (int off = 1; off < 1024; off <<= 1) {
        int add = (threadIdx.x >= off) ? sh[threadIdx.x - off] : 0;
        __syncthreads();
        sh[threadIdx.x] += add;
        __syncthreads();
    }
    if (i < N) g_rowptr[i] = sh[threadIdx.x] - v;     // exclusive
    if (threadIdx.x == 1023) g_blksum[blockIdx.x] = sh[1023];
}

__global__ void k_scan2(int B) {
    if (blockIdx.x == 0 && threadIdx.x == 0) {
        int acc = 0;
        for (int b = 0; b < B; b++) { int t = g_blksum[b]; g_blksum[b] = acc; acc += t; }
    }
}

__global__ void k_scan3(int N, int E) {
    int i = blockIdx.x * 1024 + threadIdx.x;
    if (i < N) g_rowptr[i] += g_blksum[blockIdx.x];
    if (i == 0) g_rowptr[N] = E;
}

// scatter: build CSR-permuted src and edge_attr streams
__global__ void k_scatter(const int* __restrict__ src, const int* __restrict__ dst,
                          const float4* __restrict__ ea, int E) {
    int e = blockIdx.x * blockDim.x + threadIdx.x;
    if (e >= E) return;
    int d = dst[e];
    int p = g_rowptr[d] + atomicAdd(&g_cnt[d], 1);
    g_srcp[p] = src[e];
    float4 a0 = __ldg(ea + e * 4 + 0);
    float4 a1 = __ldg(ea + e * 4 + 1);
    float4 a2 = __ldg(ea + e * 4 + 2);
    float4 a3 = __ldg(ea + e * 4 + 3);
    g_eap[p * 4 + 0] = a0;
    g_eap[p * 4 + 1] = a1;
    g_eap[p * 4 + 2] = a2;
    g_eap[p * 4 + 3] = a3;
}

// ---------------- input linear: h = x @ src_w + src_b ----------------
__global__ void k_inlin(const float* __restrict__ x, const float* __restrict__ w,
                        const float* __restrict__ b, int N) {
    int idx = blockIdx.x * blockDim.x + threadIdx.x;
    if (idx >= N * HID) return;
    int n = idx >> 6, c = idx & 63;
    const float* xr = x + n * INDIM;
    float acc = __ldg(&b[c]);
#pragma unroll
    for (int k = 0; k < INDIM; k++)
        acc = fmaf(__ldg(&xr[k]), __ldg(&w[k * HID + c]), acc);
    g_hA[idx] = acc;
}

// ---------------- aggregation: warp-per-node, f32x2 even/odd-k GEMV ----------
// dir=0: read g_hA; dir=1: read g_hB. Writes g_tmp.
// lane owns channels (2*lane, 2*lane+1). Weight k-pairs packed in registers.
__global__ void __launch_bounds__(256)
k_agg(int dir, const float* __restrict__ ew, const float* __restrict__ ebias, int N) {
    const float* hin = dir ? g_hB : g_hA;
    int warp = threadIdx.x >> 5, lane = threadIdx.x & 31;
    int n = blockIdx.x * 8 + warp;
    if (n >= N) return;

    // load ew columns for this lane's channels, pack k-pairs:
    // P0[p] = (ew[2p][c0], ew[2p+1][c0]),  P1[p] = same for c1
    unsigned long long P0[8], P1[8];
#pragma unroll
    for (int p = 0; p < 8; p++) {
        float2 wa = __ldg((const float2*)(ew + (2 * p) * HID) + lane);
        float2 wb = __ldg((const float2*)(ew + (2 * p + 1) * HID) + lane);
        P0[p] = pack2(wa.x, wb.x);
        P1[p] = pack2(wa.y, wb.y);
    }
    float2 eb = __ldg((const float2*)ebias + lane);

    int beg = g_rowptr[n], end = g_rowptr[n + 1];
    float s0 = 0.f, s1 = 0.f, t0 = 0.f, t1 = 0.f;

#pragma unroll 2
    for (int i = beg; i < end; i++) {
        int sv = __ldg(&g_srcp[i]);
        // edge i = four 16-byte elements starting at element i*4 (64 B/edge)
        const ulonglong2* ep = reinterpret_cast<const ulonglong2*>(g_eap) + (size_t)i * 4;
        ulonglong2 QA = __ldg(ep + 0);    // floats a0..a3  -> k-pairs 0,1
        ulonglong2 QB = __ldg(ep + 1);    // floats a4..a7  -> k-pairs 2,3
        float2 h = __ldg((const float2*)(hin + sv * HID) + lane);

        unsigned long long acc0 = fma2(QA.x, P0[0], pack2(eb.x, 0.f));
        unsigned long long acc1 = fma2(QA.x, P1[0], pack2(eb.y, 0.f));
        acc0 = fma2(QA.y, P0[1], acc0);
        acc1 = fma2(QA.y, P1[1], acc1);
        acc0 = fma2(QB.x, P0[2], acc0);
        acc1 = fma2(QB.x, P1[2], acc1);
        acc0 = fma2(QB.y, P0[3], acc0);
        acc1 = fma2(QB.y, P1[3], acc1);

        ulonglong2 QC = __ldg(ep + 2);    // a8..a11  -> k-pairs 4,5
        ulonglong2 QD = __ldg(ep + 3);    // a12..a15 -> k-pairs 6,7
        acc0 = fma2(QC.x, P0[4], acc0);
        acc1 = fma2(QC.x, P1[4], acc1);
        acc0 = fma2(QC.y, P0[5], acc0);
        acc1 = fma2(QC.y, P1[5], acc1);
        acc0 = fma2(QD.x, P0[6], acc0);
        acc1 = fma2(QD.x, P1[6], acc1);
        acc0 = fma2(QD.y, P0[7], acc0);
        acc1 = fma2(QD.y, P1[7], acc1);

        PF u0, u1; u0.u = acc0; u1.u = acc1;
        float v0 = u0.f2.x + u0.f2.y;
        float v1 = u1.f2.x + u1.f2.y;

        // msg = relu(h+v); eps added at the end (softmax shift-invariant).
        // No max-subtraction: msg >= 0 and O(10) -> expf cannot overflow.
        float r0 = fmaxf(h.x + v0, 0.f);
        float r1 = fmaxf(h.y + v1, 0.f);
        float w0 = __expf(r0);
        float w1 = __expf(r1);
        s0 += w0;
        s1 += w1;
        t0 = fmaf(r0, w0, t0);
        t1 = fmaf(r1, w1, t1);
    }

    float2 hs = __ldg((const float2*)(hin + n * HID) + lane);
    float o0 = (s0 > 0.f ? __fdividef(t0, s0) + 1e-7f : 0.f) + hs.x;
    float o1 = (s1 > 0.f ? __fdividef(t1, s1) + 1e-7f : 0.f) + hs.y;
    *((float2*)(g_tmp + n * HID) + lane) = make_float2(o0, o1);
}

// ---------------- MLP: Linear(64->128) -> BN -> ReLU -> Linear(128->64) -> ReLU
// reads g_tmp; dir=0: write g_hB; dir=1: write g_hA.
// 32 nodes per block, 256 threads, register-tiled
__global__ void __launch_bounds__(256)
k_mlp(int dir,
      const float* __restrict__ w1, const float* __restrict__ b1,
      const float* __restrict__ gam, const float* __restrict__ bet,
      const float* __restrict__ w2, const float* __restrict__ b2, int N) {
    float* outp = dir ? g_hA : g_hB;
    __shared__ float s_in[32][HID];     // 8 KB
    __shared__ float s_hh[32][HID2];    // 16 KB
    int tid = threadIdx.x;
    int base = blockIdx.x * 32;

    // stage 32 node rows (zero-fill past N)
    {
        const float4* src4 = (const float4*)(g_tmp + base * HID);
        float4* dst4 = (float4*)&s_in[0][0];
        long limit4 = (long)(N - base) * (HID / 4);
#pragma unroll
        for (int t = 0; t < 2; t++) {
            int i = tid + t * 256;
            dst4[i] = (i < limit4) ? __ldg(src4 + i) : make_float4(0.f, 0.f, 0.f, 0.f);
        }
    }
    __syncthreads();

    // phase 1: hh = relu(BN(in @ w1 + b1)); thread: 8 nodes x 2 adjacent j
    {
        int jp  = tid & 63;
        int grp = tid >> 6;
        float2 bb = __ldg((const float2*)b1 + jp);
        float a0[8], a1[8];
#pragma unroll
        for (int u = 0; u < 8; u++) { a0[u] = bb.x; a1[u] = bb.y; }
#pragma unroll 8
        for (int k = 0; k < HID; k++) {
            float2 w = __ldg((const float2*)(w1 + k * HID2) + jp);
#pragma unroll
            for (int u = 0; u < 8; u++) {
                float xv = s_in[grp * 8 + u][k];
                a0[u] = fmaf(xv, w.x, a0[u]);
                a1[u] = fmaf(xv, w.y, a1[u]);
            }
        }
        const float BNC = 0.9999950000375f;    // 1/sqrt(1+1e-5)
        float2 gm = __ldg((const float2*)gam + jp);
        float2 bt = __ldg((const float2*)bet + jp);
        float g0 = gm.x * BNC, g1 = gm.y * BNC;
#pragma unroll
        for (int u = 0; u < 8; u++) {
            float2 hv;
            hv.x = fmaxf(fmaf(a0[u], g0, bt.x), 0.f);
            hv.y = fmaxf(fmaf(a1[u], g1, bt.y), 0.f);
            *((float2*)&s_hh[grp * 8 + u][0] + jp) = hv;
        }
    }
    __syncthreads();

    // phase 2: y = relu(hh @ w2 + b2); thread: 4 nodes x 2 adjacent c
    {
        int cp  = tid & 31;
        int grp = tid >> 5;
        float2 bb = __ldg((const float2*)b2 + cp);
        float a0[4], a1[4];
#pragma unroll
        for (int u = 0; u < 4; u++) { a0[u] = bb.x; a1[u] = bb.y; }
#pragma unroll 8
        for (int k = 0; k < HID2; k++) {
            float2 w = __ldg((const float2*)(w2 + k * HID) + cp);
#pragma unroll
            for (int u = 0; u < 4; u++) {
                float xv = s_hh[grp * 4 + u][k];
                a0[u] = fmaf(xv, w.x, a0[u]);
                a1[u] = fmaf(xv, w.y, a1[u]);
            }
        }
#pragma unroll
        for (int u = 0; u < 4; u++) {
            int node = base + grp * 4 + u;
            if (node < N) {
                float2 ov;
                ov.x = fmaxf(a0[u], 0.f);   // outer relu
                ov.y = fmaxf(a1[u], 0.f);
                *((float2*)(outp + node * HID) + cp) = ov;
            }
        }
    }
}

// ---------------- head ----------------
__global__ void k_head(const float* __restrict__ gfeat, const int* __restrict__ ngp,
                       const float* __restrict__ hw, const float* __restrict__ hb,
                       float* __restrict__ out, int N, int gfd) {
    int n = blockIdx.x * blockDim.x + threadIdx.x;
    if (n >= N) return;
    const float* h = g_hA;   // final features land in A (A->B->A)
    float acc = __ldg(&hb[0]);
#pragma unroll 8
    for (int c = 0; c < HID; c++)
        acc = fmaf(h[n * HID + c], __ldg(&hw[c]), acc);
    int G = *ngp;
    int npg = N / G;
    int g = n / npg, r = n - g * npg;
    for (int d = 0; d < gfd; d++)
        acc = fmaf(__ldg(&gfeat[(g * gfd + d) * npg + r]), __ldg(&hw[HID + d]), acc);
    out[n] = acc;
}

// ---------------- launch ----------------
extern "C" void kernel_launch(void* const* d_in, const int* in_sizes, int n_in,
                              void* d_out, int out_size) {
    const float* x     = (const float*)d_in[0];
    const int*   eidx  = (const int*)d_in[1];
    const float* eattr = (const float*)d_in[2];
    const int*   ngp   = (const int*)d_in[3];
    const float* gfeat = (const float*)d_in[4];
    const float* src_w = (const float*)d_in[5];
    const float* src_b = (const float*)d_in[6];

    int N   = in_sizes[0] / INDIM;
    int E   = in_sizes[1] / 2;
    int gfd = in_sizes[4] / N;

    const int* src = eidx;
    const int* dst = eidx + E;

    // CSR build + permuted edge streams
    k_zero<<<(N + 255) / 256, 256>>>(N);
    k_hist<<<(E + 255) / 256, 256>>>(dst, E);
    int nb = (N + 1023) / 1024;
    k_scan1<<<nb, 1024>>>(N);
    k_scan2<<<1, 32>>>(nb);
    k_scan3<<<nb, 1024>>>(N, E);
    k_scatter<<<(E + 255) / 256, 256>>>(src, dst, (const float4*)eattr, E);

    // h0 = x @ src_w + src_b   (writes g_hA)
    k_inlin<<<(N * HID + 255) / 256, 256>>>(x, src_w, src_b, N);

    // layer 0: hA -> tmp -> hB
    k_agg<<<(N + 7) / 8, 256>>>(0, (const float*)d_in[7], (const float*)d_in[8], N);
    k_mlp<<<(N + 31) / 32, 256>>>(0,
        (const float*)d_in[9],  (const float*)d_in[10],
        (const float*)d_in[11], (const float*)d_in[12],
        (const float*)d_in[13], (const float*)d_in[14], N);

    // layer 1: hB -> tmp -> hA
    k_agg<<<(N + 7) / 8, 256>>>(1, (const float*)d_in[15], (const float*)d_in[16], N);
    k_mlp<<<(N + 31) / 32, 256>>>(1,
        (const float*)d_in[17], (const float*)d_in[18],
        (const float*)d_in[19], (const float*)d_in[20],
        (const float*)d_in[21], (const float*)d_in[22], N);

    // head
    k_head<<<(N + 255) / 256, 256>>>(gfeat, ngp,
        (const float*)d_in[23], (const float*)d_in[24],
        (float*)d_out, N, gfd);
    (void)n_in; (void)out_size;
}

// round 9
// speedup vs baseline: 1.5430x; 1.2177x over previous
#include <cuda_runtime.h>

#define NN    100000
#define EE    1600000
#define HID   64
#define HID2  128
#define EDIM  16
#define INDIM 32

// ---------------- scratch (device globals; no allocation) ----------------
__device__ float  g_hA[NN * HID];
__device__ float  g_hB[NN * HID];
__device__ float  g_tmp[NN * HID];
__device__ int    g_deg[NN];
__device__ int    g_cnt[NN];
__device__ int    g_rowptr[NN + 1];
__device__ int    g_blksum[256];
__device__ int    g_srcp[EE];          // src index permuted to CSR order
__device__ float4 g_eap[EE * 4];       // edge_attr permuted to CSR order (64 B/edge)

// ---------------- CSR build ----------------
__global__ void k_zero(int N) {
    int i = blockIdx.x * blockDim.x + threadIdx.x;
    if (i < N) { g_deg[i] = 0; g_cnt[i] = 0; }
}

__global__ void k_hist(const int* __restrict__ dst, int E) {
    int e = blockIdx.x * blockDim.x + threadIdx.x;
    if (e < E) atomicAdd(&g_deg[dst[e]], 1);
}

__global__ void k_scan1(int N) {
    __shared__ int sh[1024];
    int i = blockIdx.x * 1024 + threadIdx.x;
    int v = (i < N) ? g_deg[i] : 0;
    sh[threadIdx.x] = v;
    __syncthreads();
    for (int off = 1; off < 1024; off <<= 1) {
        int add = (threadIdx.x >= off) ? sh[threadIdx.x - off] : 0;
        __syncthreads();
        sh[threadIdx.x] += add;
        __syncthreads();
    }
    if (i < N) g_rowptr[i] = sh[threadIdx.x] - v;     // exclusive
    if (threadIdx.x == 1023) g_blksum[blockIdx.x] = sh[1023];
}

__global__ void k_scan2(int B) {
    if (blockIdx.x == 0 && threadIdx.x == 0) {
        int acc = 0;
        for (int b = 0; b < B; b++) { int t = g_blksum[b]; g_blksum[b] = acc; acc += t; }
    }
}

__global__ void k_scan3(int N, int E) {
    int i = blockIdx.x * 1024 + threadIdx.x;
    if (i < N) g_rowptr[i] += g_blksum[blockIdx.x];
    if (i == 0) g_rowptr[N] = E;
}

// scatter: build CSR-permuted src and edge_attr streams
__global__ void k_scatter(const int* __restrict__ src, const int* __restrict__ dst,
                          const float4* __restrict__ ea, int E) {
    int e = blockIdx.x * blockDim.x + threadIdx.x;
    if (e >= E) return;
    int d = dst[e];
    int p = g_rowptr[d] + atomicAdd(&g_cnt[d], 1);
    g_srcp[p] = src[e];
    float4 a0 = __ldg(ea + e * 4 + 0);
    float4 a1 = __ldg(ea + e * 4 + 1);
    float4 a2 = __ldg(ea + e * 4 + 2);
    float4 a3 = __ldg(ea + e * 4 + 3);
    g_eap[p * 4 + 0] = a0;
    g_eap[p * 4 + 1] = a1;
    g_eap[p * 4 + 2] = a2;
    g_eap[p * 4 + 3] = a3;
}

// ---------------- input linear: h = x @ src_w + src_b ----------------
__global__ void k_inlin(const float* __restrict__ x, const float* __restrict__ w,
                        const float* __restrict__ b, int N) {
    int idx = blockIdx.x * blockDim.x + threadIdx.x;
    if (idx >= N * HID) return;
    int n = idx >> 6, c = idx & 63;
    const float* xr = x + n * INDIM;
    float acc = __ldg(&b[c]);
#pragma unroll
    for (int k = 0; k < INDIM; k++)
        acc = fmaf(__ldg(&xr[k]), __ldg(&w[k * HID + c]), acc);
    g_hA[idx] = acc;
}

// ---------------- aggregation: warp-per-node, 4-edge software pipeline -------
// dir=0: read g_hA; dir=1: read g_hB. Writes g_tmp.
// lane owns channels (2*lane, 2*lane+1).
__device__ __forceinline__ void agg_edge(
    float2 h, const float4* __restrict__ ea, const float2* __restrict__ ewr,
    float eb0, float eb1, float& s0, float& s1, float& t0, float& t1)
{
    float4 a0 = __ldg(ea + 0), a1 = __ldg(ea + 1);
    float4 a2 = __ldg(ea + 2), a3 = __ldg(ea + 3);
    float av[16] = {a0.x, a0.y, a0.z, a0.w, a1.x, a1.y, a1.z, a1.w,
                    a2.x, a2.y, a2.z, a2.w, a3.x, a3.y, a3.z, a3.w};
    float v0 = eb0, v1 = eb1;
#pragma unroll
    for (int k = 0; k < EDIM; k++) {
        v0 = fmaf(av[k], ewr[k].x, v0);
        v1 = fmaf(av[k], ewr[k].y, v1);
    }
    // msg = relu(h+v); eps added at the end (softmax shift-invariant).
    // No max-subtraction: msg >= 0 and O(10) -> expf cannot overflow.
    float r0 = fmaxf(h.x + v0, 0.f);
    float r1 = fmaxf(h.y + v1, 0.f);
    float w0 = __expf(r0);
    float w1 = __expf(r1);
    s0 += w0;
    s1 += w1;
    t0 = fmaf(r0, w0, t0);
    t1 = fmaf(r1, w1, t1);
}

__global__ void __launch_bounds__(256)
k_agg(int dir, const float* __restrict__ ew, const float* __restrict__ ebias, int N) {
    const float* hin = dir ? g_hB : g_hA;
    int warp = threadIdx.x >> 5, lane = threadIdx.x & 31;
    int n = blockIdx.x * 8 + warp;
    if (n >= N) return;

    // preload ew columns for this lane's two channels
    float2 ewr[EDIM];
#pragma unroll
    for (int k = 0; k < EDIM; k++)
        ewr[k] = __ldg((const float2*)(ew + k * HID) + lane);
    float2 eb = __ldg((const float2*)ebias + lane);
    float2 hs = __ldg((const float2*)(hin + n * HID) + lane);   // self feature, hoisted

    int beg = g_rowptr[n], end = g_rowptr[n + 1];
    float s0 = 0.f, s1 = 0.f, t0 = 0.f, t1 = 0.f;

    int i = beg;
    // 4-edge pipelined main loop: batch the random h-gathers up front
    for (; i + 4 <= end; i += 4) {
        int sv0 = __ldg(&g_srcp[i + 0]);
        int sv1 = __ldg(&g_srcp[i + 1]);
        int sv2 = __ldg(&g_srcp[i + 2]);
        int sv3 = __ldg(&g_srcp[i + 3]);
        float2 h0 = __ldg((const float2*)(hin + sv0 * HID) + lane);
        float2 h1 = __ldg((const float2*)(hin + sv1 * HID) + lane);
        float2 h2 = __ldg((const float2*)(hin + sv2 * HID) + lane);
        float2 h3 = __ldg((const float2*)(hin + sv3 * HID) + lane);
        agg_edge(h0, g_eap + (size_t)(i + 0) * 4, ewr, eb.x, eb.y, s0, s1, t0, t1);
        agg_edge(h1, g_eap + (size_t)(i + 1) * 4, ewr, eb.x, eb.y, s0, s1, t0, t1);
        agg_edge(h2, g_eap + (size_t)(i + 2) * 4, ewr, eb.x, eb.y, s0, s1, t0, t1);
        agg_edge(h3, g_eap + (size_t)(i + 3) * 4, ewr, eb.x, eb.y, s0, s1, t0, t1);
    }
    for (; i < end; i++) {
        int sv = __ldg(&g_srcp[i]);
        float2 h = __ldg((const float2*)(hin + sv * HID) + lane);
        agg_edge(h, g_eap + (size_t)i * 4, ewr, eb.x, eb.y, s0, s1, t0, t1);
    }

    float o0 = (s0 > 0.f ? __fdividef(t0, s0) + 1e-7f : 0.f) + hs.x;
    float o1 = (s1 > 0.f ? __fdividef(t1, s1) + 1e-7f : 0.f) + hs.y;
    *((float2*)(g_tmp + n * HID) + lane) = make_float2(o0, o1);
}

// ---------------- MLP: Linear(64->128) -> BN -> ReLU -> Linear(128->64) -> ReLU
// reads g_tmp; dir=0: write g_hB; dir=1: write g_hA.
// 32 nodes per block, 256 threads, register-tiled, float4 LDS
__global__ void __launch_bounds__(256)
k_mlp(int dir,
      const float* __restrict__ w1, const float* __restrict__ b1,
      const float* __restrict__ gam, const float* __restrict__ bet,
      const float* __restrict__ w2, const float* __restrict__ b2, int N) {
    float* outp = dir ? g_hA : g_hB;
    __shared__ float s_in[32][HID];     // 8 KB
    __shared__ float s_hh[32][HID2];    // 16 KB
    int tid = threadIdx.x;
    int base = blockIdx.x * 32;

    // stage 32 node rows (zero-fill past N)
    {
        const float4* src4 = (const float4*)(g_tmp + base * HID);
        float4* dst4 = (float4*)&s_in[0][0];
        long limit4 = (long)(N - base) * (HID / 4);
#pragma unroll
        for (int t = 0; t < 2; t++) {
            int i = tid + t * 256;
            dst4[i] = (i < limit4) ? __ldg(src4 + i) : make_float4(0.f, 0.f, 0.f, 0.f);
        }
    }
    __syncthreads();

    // phase 1: hh = relu(BN(in @ w1 + b1)); thread: 8 nodes x 2 adjacent j
    {
        int jp  = tid & 63;
        int grp = tid >> 6;
        float2 bb = __ldg((const float2*)b1 + jp);
        float a0[8], a1[8];
#pragma unroll
        for (int u = 0; u < 8; u++) { a0[u] = bb.x; a1[u] = bb.y; }
#pragma unroll
        for (int k4 = 0; k4 < HID; k4 += 4) {
            float2 w0 = __ldg((const float2*)(w1 + (k4 + 0) * HID2) + jp);
            float2 w1v = __ldg((const float2*)(w1 + (k4 + 1) * HID2) + jp);
            float2 w2v = __ldg((const float2*)(w1 + (k4 + 2) * HID2) + jp);
            float2 w3 = __ldg((const float2*)(w1 + (k4 + 3) * HID2) + jp);
#pragma unroll
            for (int u = 0; u < 8; u++) {
                float4 xv = *(const float4*)&s_in[grp * 8 + u][k4];
                a0[u] = fmaf(xv.x, w0.x, a0[u]);
                a1[u] = fmaf(xv.x, w0.y, a1[u]);
                a0[u] = fmaf(xv.y, w1v.x, a0[u]);
                a1[u] = fmaf(xv.y, w1v.y, a1[u]);
                a0[u] = fmaf(xv.z, w2v.x, a0[u]);
                a1[u] = fmaf(xv.z, w2v.y, a1[u]);
                a0[u] = fmaf(xv.w, w3.x, a0[u]);
                a1[u] = fmaf(xv.w, w3.y, a1[u]);
            }
        }
        const float BNC = 0.9999950000375f;    // 1/sqrt(1+1e-5)
        float2 gm = __ldg((const float2*)gam + jp);
        float2 bt = __ldg((const float2*)bet + jp);
        float g0 = gm.x * BNC, g1 = gm.y * BNC;
#pragma unroll
        for (int u = 0; u < 8; u++) {
            float2 hv;
            hv.x = fmaxf(fmaf(a0[u], g0, bt.x), 0.f);
            hv.y = fmaxf(fmaf(a1[u], g1, bt.y), 0.f);
            *((float2*)&s_hh[grp * 8 + u][0] + jp) = hv;
        }
    }
    __syncthreads();

    // phase 2: y = relu(hh @ w2 + b2); thread: 4 nodes x 2 adjacent c
    {
        int cp  = tid & 31;
        int grp = tid >> 5;
        float2 bb = __ldg((const float2*)b2 + cp);
        float a0[4], a1[4];
#pragma unroll
        for (int u = 0; u < 4; u++) { a0[u] = bb.x; a1[u] = bb.y; }
#pragma unroll
        for (int k4 = 0; k4 < HID2; k4 += 4) {
            float2 w0 = __ldg((const float2*)(w2 + (k4 + 0) * HID) + cp);
            float2 w1v = __ldg((const float2*)(w2 + (k4 + 1) * HID) + cp);
            float2 w2v = __ldg((const float2*)(w2 + (k4 + 2) * HID) + cp);
            float2 w3 = __ldg((const float2*)(w2 + (k4 + 3) * HID) + cp);
#pragma unroll
            for (int u = 0; u < 4; u++) {
                float4 xv = *(const float4*)&s_hh[grp * 4 + u][k4];
                a0[u] = fmaf(xv.x, w0.x, a0[u]);
                a1[u] = fmaf(xv.x, w0.y, a1[u]);
                a0[u] = fmaf(xv.y, w1v.x, a0[u]);
                a1[u] = fmaf(xv.y, w1v.y, a1[u]);
                a0[u] = fmaf(xv.z, w2v.x, a0[u]);
                a1[u] = fmaf(xv.z, w2v.y, a1[u]);
                a0[u] = fmaf(xv.w, w3.x, a0[u]);
                a1[u] = fmaf(xv.w, w3.y, a1[u]);
            }
        }
#pragma unroll
        for (int u = 0; u < 4; u++) {
            int node = base + grp * 4 + u;
            if (node < N) {
                float2 ov;
                ov.x = fmaxf(a0[u], 0.f);   // outer relu
                ov.y = fmaxf(a1[u], 0.f);
                *((float2*)(outp + node * HID) + cp) = ov;
            }
        }
    }
}

// ---------------- head ----------------
__global__ void k_head(const float* __restrict__ gfeat, const int* __restrict__ ngp,
                       const float* __restrict__ hw, const float* __restrict__ hb,
                       float* __restrict__ out, int N, int gfd) {
    int n = blockIdx.x * blockDim.x + threadIdx.x;
    if (n >= N) return;
    const float* h = g_hA;   // final features land in A (A->B->A)
    float acc = __ldg(&hb[0]);
#pragma unroll 8
    for (int c = 0; c < HID; c++)
        acc = fmaf(h[n * HID + c], __ldg(&hw[c]), acc);
    int G = *ngp;
    int npg = N / G;
    int g = n / npg, r = n - g * npg;
    for (int d = 0; d < gfd; d++)
        acc = fmaf(__ldg(&gfeat[(g * gfd + d) * npg + r]), __ldg(&hw[HID + d]), acc);
    out[n] = acc;
}

// ---------------- launch ----------------
extern "C" void kernel_launch(void* const* d_in, const int* in_sizes, int n_in,
                              void* d_out, int out_size) {
    const float* x     = (const float*)d_in[0];
    const int*   eidx  = (const int*)d_in[1];
    const float* eattr = (const float*)d_in[2];
    const int*   ngp   = (const int*)d_in[3];
    const float* gfeat = (const float*)d_in[4];
    const float* src_w = (const float*)d_in[5];
    const float* src_b = (const float*)d_in[6];

    int N   = in_sizes[0] / INDIM;
    int E   = in_sizes[1] / 2;
    int gfd = in_sizes[4] / N;

    const int* src = eidx;
    const int* dst = eidx + E;

    // CSR build + permuted edge streams
    k_zero<<<(N + 255) / 256, 256>>>(N);
    k_hist<<<(E + 255) / 256, 256>>>(dst, E);
    int nb = (N + 1023) / 1024;
    k_scan1<<<nb, 1024>>>(N);
    k_scan2<<<1, 32>>>(nb);
    k_scan3<<<nb, 1024>>>(N, E);
    k_scatter<<<(E + 255) / 256, 256>>>(src, dst, (const float4*)eattr, E);

    // h0 = x @ src_w + src_b   (writes g_hA)
    k_inlin<<<(N * HID + 255) / 256, 256>>>(x, src_w, src_b, N);

    // layer 0: hA -> tmp -> hB
    k_agg<<<(N + 7) / 8, 256>>>(0, (const float*)d_in[7], (const float*)d_in[8], N);
    k_mlp<<<(N + 31) / 32, 256>>>(0,
        (const float*)d_in[9],  (const float*)d_in[10],
        (const float*)d_in[11], (const float*)d_in[12],
        (const float*)d_in[13], (const float*)d_in[14], N);

    // layer 1: hB -> tmp -> hA
    k_agg<<<(N + 7) / 8, 256>>>(1, (const float*)d_in[15], (const float*)d_in[16], N);
    k_mlp<<<(N + 31) / 32, 256>>>(1,
        (const float*)d_in[17], (const float*)d_in[18],
        (const float*)d_in[19], (const float*)d_in[20],
        (const float*)d_in[21], (const float*)d_in[22], N);

    // head
    k_head<<<(N + 255) / 256, 256>>>(gfeat, ngp,
        (const float*)d_in[23], (const float*)d_in[24],
        (float*)d_out, N, gfd);
    (void)n_in; (void)out_size;
}